// round 1
// baseline (speedup 1.0000x reference)
#include <cuda_runtime.h>
#include <math.h>

#define B_   2
#define N_   2048
#define DIM_ 1024
#define H_   8
#define D_   128
#define BH_  16
#define BN_  4096

// ---------------- scratch (static device globals; no allocation) ----------------
__device__ float g_xn[BN_ * DIM_];       // 16 MB normalized x
__device__ float g_q[BH_ * N_ * D_];     // 16 MB (bh, n, d)
__device__ float g_k[BH_ * N_ * D_];     // 16 MB (later overwritten with k' = elu(k)+1)
__device__ float g_v[BH_ * N_ * D_];     // 16 MB (later overwritten with v - delta)
__device__ float g_ao[BH_ * N_ * D_];    // 16 MB attention output
__device__ float g_mix[BN_ * DIM_];      // 16 MB gated mix, (b*N+n, h*128+d)
__device__ float g_rope[N_ * 64 * 2];    // cos/sin table

// ---------------- 1) row L2 norm + gamma scale ----------------
__global__ void k_norm(const float* __restrict__ x, const float* __restrict__ gamma) {
    int row = blockIdx.x;
    const float* xr = x + (size_t)row * DIM_;
    float ss = 0.f;
    for (int i = threadIdx.x; i < DIM_; i += 256) { float v = xr[i]; ss += v * v; }
    #pragma unroll
    for (int o = 16; o > 0; o >>= 1) ss += __shfl_xor_sync(0xffffffffu, ss, o);
    __shared__ float red[8];
    __shared__ float stot;
    if ((threadIdx.x & 31) == 0) red[threadIdx.x >> 5] = ss;
    __syncthreads();
    if (threadIdx.x == 0) {
        float t = 0.f;
        #pragma unroll
        for (int i = 0; i < 8; i++) t += red[i];
        stot = 32.0f / fmaxf(sqrtf(t), 1e-12f);   // sqrt(DIM)=32
    }
    __syncthreads();
    float s = stot;
    float* o = g_xn + (size_t)row * DIM_;
    for (int i = threadIdx.x; i < DIM_; i += 256) o[i] = xr[i] * s * gamma[i];
}

// ---------------- 2) QKV GEMM: [4096,3072] = g_xn[4096,1024] @ W ----------------
// 128x128 tile, BK=16, 256 threads, 8x8 micro-tile. Epilogue scatters into q/k/v.
__global__ void k_qkv_gemm(const float* __restrict__ W) {
    __shared__ float As[16][132];
    __shared__ float Bs[16][132];
    const int Kd = DIM_, NC = 3072;
    int n0 = blockIdx.x * 128;
    int m0 = blockIdx.y * 128;
    int tid = threadIdx.x;
    int tx = tid & 15, ty = tid >> 4;
    float acc[8][8] = {};
    for (int k0 = 0; k0 < Kd; k0 += 16) {
        #pragma unroll
        for (int it = 0; it < 2; it++) {
            int idx = tid + it * 256;                 // 0..511
            int am = idx >> 2, ak = (idx & 3) << 2;
            float4 a4 = *(const float4*)(g_xn + (size_t)(m0 + am) * Kd + k0 + ak);
            As[ak + 0][am] = a4.x; As[ak + 1][am] = a4.y;
            As[ak + 2][am] = a4.z; As[ak + 3][am] = a4.w;
            int bk = idx >> 5, bn = (idx & 31) << 2;
            *(float4*)&Bs[bk][bn] = *(const float4*)(W + (size_t)(k0 + bk) * NC + n0 + bn);
        }
        __syncthreads();
        #pragma unroll
        for (int kk = 0; kk < 16; kk++) {
            float a[8], b[8];
            *(float4*)(a)     = *(const float4*)&As[kk][ty * 8];
            *(float4*)(a + 4) = *(const float4*)&As[kk][ty * 8 + 4];
            *(float4*)(b)     = *(const float4*)&Bs[kk][tx * 8];
            *(float4*)(b + 4) = *(const float4*)&Bs[kk][tx * 8 + 4];
            #pragma unroll
            for (int i = 0; i < 8; i++)
                #pragma unroll
                for (int jj = 0; jj < 8; jj++)
                    acc[i][jj] = fmaf(a[i], b[jj], acc[i][jj]);
        }
        __syncthreads();
    }
    int c0 = n0 + tx * 8;          // whole 8-col strip stays in one (t,h)
    int t  = c0 >> 10;
    int h  = (c0 >> 7) & 7;
    float* dst   = (t == 0) ? g_q : (t == 1) ? g_k : g_v;
    float  scale = (t == 0) ? 0.08838834764831845f : 1.0f;  // 128^-0.5 for q
    #pragma unroll
    for (int i = 0; i < 8; i++) {
        int m = m0 + ty * 8 + i;
        int b = m >> 11, n = m & 2047;
        float* drow = dst + (((size_t)(b * H_ + h) * N_ + n) << 7) + (c0 & 127);
        #pragma unroll
        for (int jj = 0; jj < 8; jj++) drow[jj] = acc[i][jj] * scale;
    }
}

// ---------------- 3) RoPE ----------------
__global__ void k_rope_table() {
    int idx = blockIdx.x * 256 + threadIdx.x;       // N_*64
    if (idx >= N_ * 64) return;
    int n = idx >> 6, p = idx & 63;
    double freq = exp(-(double)p * (9.210340371976184 / 64.0));  // 10000^(-p/64)
    double ang = (double)n * freq;
    g_rope[idx * 2 + 0] = (float)cos(ang);
    g_rope[idx * 2 + 1] = (float)sin(ang);
}

__global__ void k_rope_apply() {
    int idx = blockIdx.x * 256 + threadIdx.x;       // BH_*N_*64 pairs
    int p = idx & 63;
    int n = (idx >> 6) & 2047;
    float c = g_rope[(n * 64 + p) * 2 + 0];
    float s = g_rope[(n * 64 + p) * 2 + 1];
    size_t base = ((size_t)(idx >> 6) << 7) + (p << 1);  // (bh*N+n)*128 + 2p
    float q1 = g_q[base], q2 = g_q[base + 1];
    g_q[base]     = q1 * c - q2 * s;
    g_q[base + 1] = q2 * c + q1 * s;
    float k1 = g_k[base], k2 = g_k[base + 1];
    g_k[base]     = k1 * c - k2 * s;
    g_k[base + 1] = k2 * c + k1 * s;
}

// ---------------- 4) causal flash attention (fp32) ----------------
// block = (qtile of 64 rows, one bh). 256 threads: r = tid>>3 (+32 for 2nd row),
// j = tid&7 -> interleaved cols/dims (bank-conflict-free padded smem).
#define FL_SMEM ((3 * 64 * 132 + 64 * 65) * 4)
__global__ void k_flash() {
    extern __shared__ float sm[];
    float* Qs = sm;
    float* Ks = sm + 64 * 132;
    float* Vs = sm + 2 * 64 * 132;
    float* Ps = sm + 3 * 64 * 132;      // 64 x 65
    int bh = blockIdx.y;
    int q0 = blockIdx.x << 6;
    int tid = threadIdx.x;
    int r = tid >> 3, j = tid & 7;
    const float* Qg = g_q + ((size_t)bh * N_ + q0) * D_;
    #pragma unroll
    for (int it = 0; it < 8; it++) {
        int idx = tid + it * 256;
        int row = idx >> 5, col = (idx & 31) << 2;
        *(float4*)&Qs[row * 132 + col] = *(const float4*)(Qg + row * D_ + col);
    }
    float m0v = -INFINITY, m1v = -INFINITY, l0 = 0.f, l1 = 0.f;
    float o0[16] = {}, o1[16] = {};
    int nkt = blockIdx.x + 1;
    for (int kt = 0; kt < nkt; kt++) {
        __syncthreads();
        const float* Kg = g_k + ((size_t)bh * N_ + (kt << 6)) * D_;
        const float* Vg = g_v + ((size_t)bh * N_ + (kt << 6)) * D_;
        #pragma unroll
        for (int it = 0; it < 8; it++) {
            int idx = tid + it * 256;
            int row = idx >> 5, col = (idx & 31) << 2;
            *(float4*)&Ks[row * 132 + col] = *(const float4*)(Kg + row * D_ + col);
            *(float4*)&Vs[row * 132 + col] = *(const float4*)(Vg + row * D_ + col);
        }
        __syncthreads();
        float s0[8] = {}, s1[8] = {};
        #pragma unroll 4
        for (int kk = 0; kk < 128; kk++) {
            float qa = Qs[r * 132 + kk];
            float qb = Qs[(r + 32) * 132 + kk];
            #pragma unroll
            for (int c8 = 0; c8 < 8; c8++) {
                float kv = Ks[(j + (c8 << 3)) * 132 + kk];
                s0[c8] = fmaf(qa, kv, s0[c8]);
                s1[c8] = fmaf(qb, kv, s1[c8]);
            }
        }
        if (kt == blockIdx.x) {   // causal mask on diagonal tile
            #pragma unroll
            for (int c8 = 0; c8 < 8; c8++) {
                int col = (kt << 6) + j + (c8 << 3);
                if (col > q0 + r)      s0[c8] = -1e30f;
                if (col > q0 + r + 32) s1[c8] = -1e30f;
            }
        }
        float tm0 = s0[0], tm1 = s1[0];
        #pragma unroll
        for (int c8 = 1; c8 < 8; c8++) { tm0 = fmaxf(tm0, s0[c8]); tm1 = fmaxf(tm1, s1[c8]); }
        #pragma unroll
        for (int o = 1; o < 8; o <<= 1) {
            tm0 = fmaxf(tm0, __shfl_xor_sync(0xffffffffu, tm0, o));
            tm1 = fmaxf(tm1, __shfl_xor_sync(0xffffffffu, tm1, o));
        }
        float mn0 = fmaxf(m0v, tm0), mn1 = fmaxf(m1v, tm1);
        float sc0 = __expf(m0v - mn0), sc1 = __expf(m1v - mn1);
        l0 *= sc0; l1 *= sc1;
        #pragma unroll
        for (int di = 0; di < 16; di++) { o0[di] *= sc0; o1[di] *= sc1; }
        float ps0 = 0.f, ps1 = 0.f;
        #pragma unroll
        for (int c8 = 0; c8 < 8; c8++) {
            float p0 = __expf(s0[c8] - mn0), p1 = __expf(s1[c8] - mn1);
            s0[c8] = p0; s1[c8] = p1; ps0 += p0; ps1 += p1;
        }
        #pragma unroll
        for (int o = 1; o < 8; o <<= 1) {
            ps0 += __shfl_xor_sync(0xffffffffu, ps0, o);
            ps1 += __shfl_xor_sync(0xffffffffu, ps1, o);
        }
        l0 += ps0; l1 += ps1; m0v = mn0; m1v = mn1;
        #pragma unroll
        for (int c8 = 0; c8 < 8; c8++) {
            Ps[r * 65 + j + (c8 << 3)]        = s0[c8];
            Ps[(r + 32) * 65 + j + (c8 << 3)] = s1[c8];
        }
        __syncwarp();   // Ps rows are produced/consumed by the same 8-lane groups
        #pragma unroll 2
        for (int c = 0; c < 64; c++) {
            float p0 = Ps[r * 65 + c], p1 = Ps[(r + 32) * 65 + c];
            const float* vr = &Vs[c * 132 + j];
            #pragma unroll
            for (int di = 0; di < 16; di++) {
                float vv = vr[di << 3];
                o0[di] = fmaf(p0, vv, o0[di]);
                o1[di] = fmaf(p1, vv, o1[di]);
            }
        }
    }
    float i0 = 1.f / l0, i1 = 1.f / l1;
    float* Og = g_ao + ((size_t)bh * N_ + q0) * D_;
    #pragma unroll
    for (int di = 0; di < 16; di++) {
        Og[r * D_ + j + (di << 3)]        = o0[di] * i0;
        Og[(r + 32) * D_ + j + (di << 3)] = o1[di] * i1;
    }
}

// ---------------- 5a) memory read + gate mix ----------------
__global__ void k_mix(const float* __restrict__ past_kv, const float* __restrict__ past_norm,
                      const float* __restrict__ gates) {
    int gid = blockIdx.x;               // bh*N + n
    int bh = gid >> 11, n = gid & 2047;
    int d = threadIdx.x;                // 128 threads
    __shared__ float qp[128];
    __shared__ float red[4];
    size_t idx = ((size_t)gid << 7) + d;
    float qv = g_q[idx];
    float e = qv > 0.f ? qv + 1.f : expf(qv);   // elu(q)+1
    qp[d] = e;
    float prod = e * past_norm[(bh << 7) + d];
    #pragma unroll
    for (int o = 16; o > 0; o >>= 1) prod += __shfl_xor_sync(0xffffffffu, prod, o);
    if ((d & 31) == 0) red[d >> 5] = prod;
    __syncthreads();
    float mnorm = fmaxf(red[0] + red[1] + red[2] + red[3], 1e-10f);
    const float* pkv = past_kv + ((size_t)bh << 14) + d;
    float mo = 0.f;
    #pragma unroll 8
    for (int kd = 0; kd < 128; kd++) mo = fmaf(qp[kd], pkv[(size_t)kd << 7], mo);
    float g = 1.f / (1.f + expf(-gates[bh & 7]));
    float res = g_ao[idx] * g + (mo / mnorm) * (1.f - g);
    int b = bh >> 3, h = bh & 7;
    g_mix[((size_t)((b << 11) + n) << 10) + (h << 7) + d] = res;
}

// ---------------- 5b) delta update: k' = elu(k)+1 (in place), v -= delta ----------------
__global__ void k_delta(const float* __restrict__ past_kv, const float* __restrict__ past_norm) {
    int gid = blockIdx.x;
    int bh = gid >> 11;
    int d = threadIdx.x;
    __shared__ float kp[128];
    __shared__ float red[4];
    size_t idx = ((size_t)gid << 7) + d;
    float kv = g_k[idx];
    float e = kv > 0.f ? kv + 1.f : expf(kv);
    kp[d] = e;
    g_k[idx] = e;
    float prod = e * past_norm[(bh << 7) + d];
    #pragma unroll
    for (int o = 16; o > 0; o >>= 1) prod += __shfl_xor_sync(0xffffffffu, prod, o);
    if ((d & 31) == 0) red[d >> 5] = prod;
    __syncthreads();
    float dnorm = fmaxf(red[0] + red[1] + red[2] + red[3], 1e-10f);
    const float* pkv = past_kv + ((size_t)bh << 14) + d;
    float dv = 0.f;
    #pragma unroll 8
    for (int kd = 0; kd < 128; kd++) dv = fmaf(kp[kd], pkv[(size_t)kd << 7], dv);
    g_v[idx] = g_v[idx] - dv / dnorm;
}

// ---------------- 6) new_kv / new_norm ----------------
#define OUT_KV_OFF   4194304
#define OUT_NORM_OFF (4194304 + 262144)
__global__ void k_init_out(const float* __restrict__ past_kv, const float* __restrict__ past_norm,
                           float* __restrict__ out) {
    int i = blockIdx.x * 256 + threadIdx.x;
    if (i < BH_ * D_ * D_) out[OUT_KV_OFF + i] = past_kv[i];
    if (i < BH_ * D_)      out[OUT_NORM_OFF + i] = past_norm[i];
}

__global__ void k_newnorm(float* __restrict__ out) {
    int bh = blockIdx.y, chunk = blockIdx.x;
    int d = threadIdx.x;
    const float* kp = g_k + ((size_t)bh * N_ + chunk * 128) * D_ + d;
    float s = 0.f;
    #pragma unroll 4
    for (int nn = 0; nn < 128; nn++) s += kp[(size_t)nn << 7];
    atomicAdd(&out[OUT_NORM_OFF + (bh << 7) + d], s);
}

__global__ void k_newkv(float* __restrict__ out) {
    __shared__ float Ksh[16][132], Vsh[16][132];
    int bh = blockIdx.y;
    int n0 = blockIdx.x << 7;           // 16 chunks of 128
    int tid = threadIdx.x, tx = tid & 15, ty = tid >> 4;
    float acc[8][8] = {};
    const float* kbase = g_k + ((size_t)bh * N_ + n0) * D_;
    const float* vbase = g_v + ((size_t)bh * N_ + n0) * D_;
    for (int nt = 0; nt < 128; nt += 16) {
        #pragma unroll
        for (int it = 0; it < 2; it++) {
            int idx = tid + it * 256;
            int nn = idx >> 5, col = (idx & 31) << 2;
            *(float4*)&Ksh[nn][col] = *(const float4*)(kbase + (size_t)(nt + nn) * D_ + col);
            *(float4*)&Vsh[nn][col] = *(const float4*)(vbase + (size_t)(nt + nn) * D_ + col);
        }
        __syncthreads();
        #pragma unroll
        for (int nn = 0; nn < 16; nn++) {
            float a[8], b[8];
            *(float4*)(a)     = *(const float4*)&Ksh[nn][ty * 8];
            *(float4*)(a + 4) = *(const float4*)&Ksh[nn][ty * 8 + 4];
            *(float4*)(b)     = *(const float4*)&Vsh[nn][tx * 8];
            *(float4*)(b + 4) = *(const float4*)&Vsh[nn][tx * 8 + 4];
            #pragma unroll
            for (int i = 0; i < 8; i++)
                #pragma unroll
                for (int jj = 0; jj < 8; jj++)
                    acc[i][jj] = fmaf(a[i], b[jj], acc[i][jj]);
        }
        __syncthreads();
    }
    float* okv = out + OUT_KV_OFF + ((size_t)bh << 14);
    #pragma unroll
    for (int i = 0; i < 8; i++)
        #pragma unroll
        for (int jj = 0; jj < 8; jj++)
            atomicAdd(&okv[(ty * 8 + i) * 128 + tx * 8 + jj], acc[i][jj]);
}

// ---------------- 7) output GEMM: d_out[4096,1024] = g_mix @ w_out ----------------
__global__ void k_out_gemm(const float* __restrict__ W, float* __restrict__ out) {
    __shared__ float As[16][132];
    __shared__ float Bs[16][132];
    const int Kd = DIM_, NC = 1024;
    int n0 = blockIdx.x * 128;
    int m0 = blockIdx.y * 128;
    int tid = threadIdx.x;
    int tx = tid & 15, ty = tid >> 4;
    float acc[8][8] = {};
    for (int k0 = 0; k0 < Kd; k0 += 16) {
        #pragma unroll
        for (int it = 0; it < 2; it++) {
            int idx = tid + it * 256;
            int am = idx >> 2, ak = (idx & 3) << 2;
            float4 a4 = *(const float4*)(g_mix + (size_t)(m0 + am) * Kd + k0 + ak);
            As[ak + 0][am] = a4.x; As[ak + 1][am] = a4.y;
            As[ak + 2][am] = a4.z; As[ak + 3][am] = a4.w;
            int bk = idx >> 5, bn = (idx & 31) << 2;
            *(float4*)&Bs[bk][bn] = *(const float4*)(W + (size_t)(k0 + bk) * NC + n0 + bn);
        }
        __syncthreads();
        #pragma unroll
        for (int kk = 0; kk < 16; kk++) {
            float a[8], b[8];
            *(float4*)(a)     = *(const float4*)&As[kk][ty * 8];
            *(float4*)(a + 4) = *(const float4*)&As[kk][ty * 8 + 4];
            *(float4*)(b)     = *(const float4*)&Bs[kk][tx * 8];
            *(float4*)(b + 4) = *(const float4*)&Bs[kk][tx * 8 + 4];
            #pragma unroll
            for (int i = 0; i < 8; i++)
                #pragma unroll
                for (int jj = 0; jj < 8; jj++)
                    acc[i][jj] = fmaf(a[i], b[jj], acc[i][jj]);
        }
        __syncthreads();
    }
    #pragma unroll
    for (int i = 0; i < 8; i++) {
        int m = m0 + ty * 8 + i;
        float* orow = out + (size_t)m * NC + n0 + tx * 8;
        #pragma unroll
        for (int jj = 0; jj < 8; jj++) orow[jj] = acc[i][jj];
    }
}

// ---------------- launch ----------------
extern "C" void kernel_launch(void* const* d_in, const int* in_sizes, int n_in,
                              void* d_out, int out_size) {
    const float* x         = (const float*)d_in[0];
    const float* gamma     = (const float*)d_in[1];
    const float* w_qkv     = (const float*)d_in[2];
    const float* w_out     = (const float*)d_in[3];
    const float* gates     = (const float*)d_in[4];
    const float* past_kv   = (const float*)d_in[5];
    const float* past_norm = (const float*)d_in[6];
    float* out = (float*)d_out;

    cudaFuncSetAttribute(k_flash, cudaFuncAttributeMaxDynamicSharedMemorySize, FL_SMEM);

    k_norm<<<BN_, 256>>>(x, gamma);
    dim3 gq(24, 32);
    k_qkv_gemm<<<gq, 256>>>(w_qkv);
    k_rope_table<<<(N_ * 64) / 256, 256>>>();
    k_rope_apply<<<(BH_ * N_ * 64) / 256, 256>>>();
    dim3 gf(32, 16);
    k_flash<<<gf, 256, FL_SMEM>>>();
    k_mix<<<BH_ * N_, 128>>>(past_kv, past_norm, gates);
    k_delta<<<BH_ * N_, 128>>>(past_kv, past_norm);
    k_init_out<<<1024, 256>>>(past_kv, past_norm, out);
    dim3 gn(16, 16);
    k_newnorm<<<gn, 128>>>(out);
    k_newkv<<<gn, 256>>>(out);
    dim3 go(8, 32);
    k_out_gemm<<<go, 256>>>(w_out, out);
}

// round 2
// speedup vs baseline: 2.2463x; 2.2463x over previous
#include <cuda_runtime.h>
#include <math.h>
#include <stdint.h>

#define B_   2
#define N_   2048
#define DIM_ 1024
#define H_   8
#define D_   128
#define BH_  16
#define BN_  4096

// ---------------- scratch (static device globals; no allocation) ----------------
__device__ float g_xn[BN_ * DIM_];       // normalized x
__device__ float g_q[BH_ * N_ * D_];     // (bh, n, d)
__device__ float g_k[BH_ * N_ * D_];     // (later overwritten with k' = elu(k)+1)
__device__ float g_v[BH_ * N_ * D_];     // (later overwritten with v - delta)
__device__ float g_ao[BH_ * N_ * D_];    // attention output
__device__ float g_mix[BN_ * DIM_];      // gated mix, (b*N+n, h*128+d)
__device__ float g_rope[N_ * 64 * 2];    // cos/sin table

// ---------------- tf32 mma helpers ----------------
__device__ __forceinline__ uint32_t f2t(float x) {
    uint32_t r; asm("cvt.rna.tf32.f32 %0, %1;" : "=r"(r) : "f"(x)); return r;
}
__device__ __forceinline__ void mma8(float* d,
        uint32_t a0, uint32_t a1, uint32_t a2, uint32_t a3,
        uint32_t b0, uint32_t b1) {
    asm volatile(
        "mma.sync.aligned.m16n8k8.row.col.f32.tf32.tf32.f32 "
        "{%0,%1,%2,%3},{%4,%5,%6,%7},{%8,%9},{%0,%1,%2,%3};"
        : "+f"(d[0]), "+f"(d[1]), "+f"(d[2]), "+f"(d[3])
        : "r"(a0), "r"(a1), "r"(a2), "r"(a3), "r"(b0), "r"(b1));
}

// ---------------- 1) row L2 norm + gamma scale ----------------
__global__ void k_norm(const float* __restrict__ x, const float* __restrict__ gamma) {
    int row = blockIdx.x;
    const float* xr = x + (size_t)row * DIM_;
    float ss = 0.f;
    for (int i = threadIdx.x; i < DIM_; i += 256) { float v = xr[i]; ss += v * v; }
    #pragma unroll
    for (int o = 16; o > 0; o >>= 1) ss += __shfl_xor_sync(0xffffffffu, ss, o);
    __shared__ float red[8];
    __shared__ float stot;
    if ((threadIdx.x & 31) == 0) red[threadIdx.x >> 5] = ss;
    __syncthreads();
    if (threadIdx.x == 0) {
        float t = 0.f;
        #pragma unroll
        for (int i = 0; i < 8; i++) t += red[i];
        stot = 32.0f / fmaxf(sqrtf(t), 1e-12f);
    }
    __syncthreads();
    float s = stot;
    float* o = g_xn + (size_t)row * DIM_;
    for (int i = threadIdx.x; i < DIM_; i += 256) o[i] = xr[i] * s * gamma[i];
}

// ---------------- 2) QKV GEMM (tf32 mma): [4096,3072] = g_xn @ W ----------------
// 128x128 tile, BK=32, 8 warps, warp tile 64x32 (4 m16-tiles x 4 n8-tiles)
__global__ void k_qkv_mma(const float* __restrict__ W) {
    __shared__ uint32_t As[128][40];   // [m][k], stride 40 (=8 mod 32 -> frag loads conflict-free)
    __shared__ uint32_t Bs[32][136];   // [k][n], stride 136
    int n0 = blockIdx.x * 128, m0 = blockIdx.y * 128;
    int tid = threadIdx.x, lane = tid & 31, wid = tid >> 5;
    int wm = (wid >> 2) * 64, wn = (wid & 3) * 32;
    int g = lane >> 2, t = lane & 3;
    float acc[4][4][4] = {};
    for (int k0 = 0; k0 < 1024; k0 += 32) {
        #pragma unroll
        for (int it = 0; it < 4; it++) {
            int idx = tid + it * 256;
            int am = idx >> 3, ak = (idx & 7) << 2;
            float4 a4 = *(const float4*)(g_xn + (size_t)(m0 + am) * 1024 + k0 + ak);
            uint4 au; au.x = f2t(a4.x); au.y = f2t(a4.y); au.z = f2t(a4.z); au.w = f2t(a4.w);
            *(uint4*)&As[am][ak] = au;
            int bk = idx >> 5, bn = (idx & 31) << 2;
            float4 b4 = *(const float4*)(W + (size_t)(k0 + bk) * 3072 + n0 + bn);
            uint4 bu; bu.x = f2t(b4.x); bu.y = f2t(b4.y); bu.z = f2t(b4.z); bu.w = f2t(b4.w);
            *(uint4*)&Bs[bk][bn] = bu;
        }
        __syncthreads();
        #pragma unroll
        for (int ks = 0; ks < 4; ks++) {
            int kc = ks * 8;
            uint32_t bf0[4], bf1[4];
            #pragma unroll
            for (int nt = 0; nt < 4; nt++) {
                bf0[nt] = Bs[kc + t][wn + nt * 8 + g];
                bf1[nt] = Bs[kc + t + 4][wn + nt * 8 + g];
            }
            #pragma unroll
            for (int mt = 0; mt < 4; mt++) {
                int mr = wm + mt * 16 + g;
                uint32_t a0 = As[mr][kc + t];
                uint32_t a1 = As[mr + 8][kc + t];
                uint32_t a2 = As[mr][kc + t + 4];
                uint32_t a3 = As[mr + 8][kc + t + 4];
                #pragma unroll
                for (int nt = 0; nt < 4; nt++)
                    mma8(acc[mt][nt], a0, a1, a2, a3, bf0[nt], bf1[nt]);
            }
        }
        __syncthreads();
    }
    // epilogue: scatter into q/k/v (q scaled by 128^-0.5)
    #pragma unroll
    for (int mt = 0; mt < 4; mt++) {
        int mA = m0 + wm + mt * 16 + g;
        #pragma unroll
        for (int nt = 0; nt < 4; nt++) {
            int c = n0 + wn + nt * 8 + t * 2;
            int t3 = c >> 10, h = (c >> 7) & 7, dd = c & 127;
            float* dst = (t3 == 0) ? g_q : (t3 == 1) ? g_k : g_v;
            float sc = (t3 == 0) ? 0.08838834764831845f : 1.0f;
            {
                int b = mA >> 11, n = mA & 2047;
                float* p = dst + (((size_t)(b * 8 + h) * 2048 + n) << 7) + dd;
                *(float2*)p = make_float2(acc[mt][nt][0] * sc, acc[mt][nt][1] * sc);
            }
            {
                int m2 = mA + 8; int b = m2 >> 11, n = m2 & 2047;
                float* p = dst + (((size_t)(b * 8 + h) * 2048 + n) << 7) + dd;
                *(float2*)p = make_float2(acc[mt][nt][2] * sc, acc[mt][nt][3] * sc);
            }
        }
    }
}

// ---------------- 3) RoPE ----------------
__global__ void k_rope_table() {
    int idx = blockIdx.x * 256 + threadIdx.x;
    if (idx >= N_ * 64) return;
    int n = idx >> 6, p = idx & 63;
    double freq = exp(-(double)p * (9.210340371976184 / 64.0));
    double ang = (double)n * freq;
    g_rope[idx * 2 + 0] = (float)cos(ang);
    g_rope[idx * 2 + 1] = (float)sin(ang);
}

__global__ void k_rope_apply() {
    int idx = blockIdx.x * 256 + threadIdx.x;
    int p = idx & 63;
    int n = (idx >> 6) & 2047;
    float c = g_rope[(n * 64 + p) * 2 + 0];
    float s = g_rope[(n * 64 + p) * 2 + 1];
    size_t base = ((size_t)(idx >> 6) << 7) + (p << 1);
    float q1 = g_q[base], q2 = g_q[base + 1];
    g_q[base]     = q1 * c - q2 * s;
    g_q[base + 1] = q2 * c + q1 * s;
    float k1 = g_k[base], k2 = g_k[base + 1];
    g_k[base]     = k1 * c - k2 * s;
    g_k[base + 1] = k2 * c + k1 * s;
}

// ---------------- 4) causal flash attention (tf32 mma) ----------------
// block: one bh, 128 q rows, 8 warps (warp w -> rows w*16..w*16+15), KV tiles of 64.
#define QS_STRIDE 136
#define KS_STRIDE 132
#define VS_STRIDE 136
#define PS_STRIDE 72
#define FL2_KS_OFF (128 * QS_STRIDE)
#define FL2_VS_OFF (FL2_KS_OFF + 64 * KS_STRIDE)
#define FL2_PS_OFF (FL2_VS_OFF + 64 * VS_STRIDE)
#define FL2_WORDS  (FL2_PS_OFF + 128 * PS_STRIDE)
#define FL2_SMEM   (FL2_WORDS * 4)

__global__ void k_flash_mma() {
    extern __shared__ uint32_t sm2[];
    uint32_t* Qs = sm2;                  // [128][136]  [m][d]
    uint32_t* Ks = sm2 + FL2_KS_OFF;     // [64][132]   [key][d]
    uint32_t* Vs = sm2 + FL2_VS_OFF;     // [64][136]   [key][d]
    uint32_t* Ps = sm2 + FL2_PS_OFF;     // [128][72]   [m][key]
    int bh = blockIdx.y;
    int qt = 15 - blockIdx.x;            // heavy tiles first
    int q0 = qt << 7;
    int tid = threadIdx.x, lane = tid & 31, wid = tid >> 5;
    int g = lane >> 2, t = lane & 3;
    const float* Qg = g_q + ((size_t)bh * N_ + q0) * D_;
    #pragma unroll
    for (int it = 0; it < 16; it++) {
        int idx = tid + it * 256;
        int row = idx >> 5, col = (idx & 31) << 2;
        float4 q4 = *(const float4*)(Qg + (size_t)row * D_ + col);
        uint4 u; u.x = f2t(q4.x); u.y = f2t(q4.y); u.z = f2t(q4.z); u.w = f2t(q4.w);
        *(uint4*)&Qs[row * QS_STRIDE + col] = u;
    }
    float oacc[16][4] = {};
    float m0v = -INFINITY, m1v = -INFINITY, l0 = 0.f, l1 = 0.f;
    int row0 = q0 + wid * 16 + g;
    int prow0 = (wid * 16 + g) * PS_STRIDE;
    int prow1 = (wid * 16 + g + 8) * PS_STRIDE;
    int qrow0 = (wid * 16 + g) * QS_STRIDE;
    int qrow1 = (wid * 16 + g + 8) * QS_STRIDE;
    int nkt = 2 * qt + 2;
    for (int kt = 0; kt < nkt; kt++) {
        __syncthreads();
        const float* Kg = g_k + ((size_t)bh * N_ + kt * 64) * D_;
        const float* Vg = g_v + ((size_t)bh * N_ + kt * 64) * D_;
        #pragma unroll
        for (int it = 0; it < 8; it++) {
            int idx = tid + it * 256;
            int row = idx >> 5, col = (idx & 31) << 2;
            float4 k4 = *(const float4*)(Kg + (size_t)row * D_ + col);
            uint4 ku; ku.x = f2t(k4.x); ku.y = f2t(k4.y); ku.z = f2t(k4.z); ku.w = f2t(k4.w);
            *(uint4*)&Ks[row * KS_STRIDE + col] = ku;
            float4 v4 = *(const float4*)(Vg + (size_t)row * D_ + col);
            uint4 vu; vu.x = f2t(v4.x); vu.y = f2t(v4.y); vu.z = f2t(v4.z); vu.w = f2t(v4.w);
            *(uint4*)&Vs[row * VS_STRIDE + col] = vu;
        }
        __syncthreads();
        // S = Q K^T  (16 x 64 per warp)
        float sacc[8][4] = {};
        #pragma unroll
        for (int ks = 0; ks < 16; ks++) {
            int kc = ks * 8;
            uint32_t a0 = Qs[qrow0 + kc + t];
            uint32_t a1 = Qs[qrow1 + kc + t];
            uint32_t a2 = Qs[qrow0 + kc + t + 4];
            uint32_t a3 = Qs[qrow1 + kc + t + 4];
            #pragma unroll
            for (int nt = 0; nt < 8; nt++) {
                uint32_t b0 = Ks[(nt * 8 + g) * KS_STRIDE + kc + t];
                uint32_t b1 = Ks[(nt * 8 + g) * KS_STRIDE + kc + t + 4];
                mma8(sacc[nt], a0, a1, a2, a3, b0, b1);
            }
        }
        if (kt >= 2 * qt) {   // causal mask (diagonal region)
            #pragma unroll
            for (int nt = 0; nt < 8; nt++) {
                int cb = kt * 64 + nt * 8 + t * 2;
                if (cb     > row0)     sacc[nt][0] = -1e30f;
                if (cb + 1 > row0)     sacc[nt][1] = -1e30f;
                if (cb     > row0 + 8) sacc[nt][2] = -1e30f;
                if (cb + 1 > row0 + 8) sacc[nt][3] = -1e30f;
            }
        }
        // online softmax (per-row stats duplicated across the quad)
        float tm0 = -1e30f, tm1 = -1e30f;
        #pragma unroll
        for (int nt = 0; nt < 8; nt++) {
            tm0 = fmaxf(tm0, fmaxf(sacc[nt][0], sacc[nt][1]));
            tm1 = fmaxf(tm1, fmaxf(sacc[nt][2], sacc[nt][3]));
        }
        tm0 = fmaxf(tm0, __shfl_xor_sync(0xffffffffu, tm0, 1));
        tm0 = fmaxf(tm0, __shfl_xor_sync(0xffffffffu, tm0, 2));
        tm1 = fmaxf(tm1, __shfl_xor_sync(0xffffffffu, tm1, 1));
        tm1 = fmaxf(tm1, __shfl_xor_sync(0xffffffffu, tm1, 2));
        float mn0 = fmaxf(m0v, tm0), mn1 = fmaxf(m1v, tm1);
        float sc0 = __expf(m0v - mn0), sc1 = __expf(m1v - mn1);
        m0v = mn0; m1v = mn1;
        #pragma unroll
        for (int nt = 0; nt < 16; nt++) {
            oacc[nt][0] *= sc0; oacc[nt][1] *= sc0;
            oacc[nt][2] *= sc1; oacc[nt][3] *= sc1;
        }
        float ps0 = 0.f, ps1 = 0.f;
        #pragma unroll
        for (int nt = 0; nt < 8; nt++) {
            float p0 = __expf(sacc[nt][0] - mn0), p1 = __expf(sacc[nt][1] - mn0);
            float p2 = __expf(sacc[nt][2] - mn1), p3 = __expf(sacc[nt][3] - mn1);
            ps0 += p0 + p1; ps1 += p2 + p3;
            uint2 w0; w0.x = f2t(p0); w0.y = f2t(p1);
            *(uint2*)&Ps[prow0 + nt * 8 + t * 2] = w0;
            uint2 w1; w1.x = f2t(p2); w1.y = f2t(p3);
            *(uint2*)&Ps[prow1 + nt * 8 + t * 2] = w1;
        }
        ps0 += __shfl_xor_sync(0xffffffffu, ps0, 1);
        ps0 += __shfl_xor_sync(0xffffffffu, ps0, 2);
        ps1 += __shfl_xor_sync(0xffffffffu, ps1, 1);
        ps1 += __shfl_xor_sync(0xffffffffu, ps1, 2);
        l0 = l0 * sc0 + ps0; l1 = l1 * sc1 + ps1;
        __syncwarp();
        // O += P V   (16 x 128 per warp)
        #pragma unroll
        for (int ks = 0; ks < 8; ks++) {
            int kc = ks * 8;
            uint32_t a0 = Ps[prow0 + kc + t];
            uint32_t a1 = Ps[prow1 + kc + t];
            uint32_t a2 = Ps[prow0 + kc + t + 4];
            uint32_t a3 = Ps[prow1 + kc + t + 4];
            #pragma unroll
            for (int nt = 0; nt < 16; nt++) {
                uint32_t b0 = Vs[(kc + t) * VS_STRIDE + nt * 8 + g];
                uint32_t b1 = Vs[(kc + t + 4) * VS_STRIDE + nt * 8 + g];
                mma8(oacc[nt], a0, a1, a2, a3, b0, b1);
            }
        }
    }
    float i0 = 1.f / l0, i1 = 1.f / l1;
    float* Og = g_ao + ((size_t)bh * N_ + q0 + wid * 16) * D_;
    #pragma unroll
    for (int nt = 0; nt < 16; nt++) {
        *(float2*)&Og[g * D_ + nt * 8 + t * 2] =
            make_float2(oacc[nt][0] * i0, oacc[nt][1] * i0);
        *(float2*)&Og[(g + 8) * D_ + nt * 8 + t * 2] =
            make_float2(oacc[nt][2] * i1, oacc[nt][3] * i1);
    }
}

// ---------------- 5a) memory read + gate mix ----------------
__global__ void k_mix(const float* __restrict__ past_kv, const float* __restrict__ past_norm,
                      const float* __restrict__ gates) {
    int gid = blockIdx.x;
    int bh = gid >> 11, n = gid & 2047;
    int d = threadIdx.x;
    __shared__ float qp[128];
    __shared__ float red[4];
    size_t idx = ((size_t)gid << 7) + d;
    float qv = g_q[idx];
    float e = qv > 0.f ? qv + 1.f : expf(qv);
    qp[d] = e;
    float prod = e * past_norm[(bh << 7) + d];
    #pragma unroll
    for (int o = 16; o > 0; o >>= 1) prod += __shfl_xor_sync(0xffffffffu, prod, o);
    if ((d & 31) == 0) red[d >> 5] = prod;
    __syncthreads();
    float mnorm = fmaxf(red[0] + red[1] + red[2] + red[3], 1e-10f);
    const float* pkv = past_kv + ((size_t)bh << 14) + d;
    float mo = 0.f;
    #pragma unroll 8
    for (int kd = 0; kd < 128; kd++) mo = fmaf(qp[kd], pkv[(size_t)kd << 7], mo);
    float gte = 1.f / (1.f + expf(-gates[bh & 7]));
    float res = g_ao[idx] * gte + (mo / mnorm) * (1.f - gte);
    int b = bh >> 3, h = bh & 7;
    g_mix[((size_t)((b << 11) + n) << 10) + (h << 7) + d] = res;
}

// ---------------- 5b) delta update ----------------
__global__ void k_delta(const float* __restrict__ past_kv, const float* __restrict__ past_norm) {
    int gid = blockIdx.x;
    int bh = gid >> 11;
    int d = threadIdx.x;
    __shared__ float kp[128];
    __shared__ float red[4];
    size_t idx = ((size_t)gid << 7) + d;
    float kv = g_k[idx];
    float e = kv > 0.f ? kv + 1.f : expf(kv);
    kp[d] = e;
    g_k[idx] = e;
    float prod = e * past_norm[(bh << 7) + d];
    #pragma unroll
    for (int o = 16; o > 0; o >>= 1) prod += __shfl_xor_sync(0xffffffffu, prod, o);
    if ((d & 31) == 0) red[d >> 5] = prod;
    __syncthreads();
    float dnorm = fmaxf(red[0] + red[1] + red[2] + red[3], 1e-10f);
    const float* pkv = past_kv + ((size_t)bh << 14) + d;
    float dv = 0.f;
    #pragma unroll 8
    for (int kd = 0; kd < 128; kd++) dv = fmaf(kp[kd], pkv[(size_t)kd << 7], dv);
    g_v[idx] = g_v[idx] - dv / dnorm;
}

// ---------------- 6) new_kv / new_norm ----------------
#define OUT_KV_OFF   4194304
#define OUT_NORM_OFF (4194304 + 262144)
__global__ void k_init_out(const float* __restrict__ past_kv, const float* __restrict__ past_norm,
                           float* __restrict__ out) {
    int i = blockIdx.x * 256 + threadIdx.x;
    if (i < BH_ * D_ * D_) out[OUT_KV_OFF + i] = past_kv[i];
    if (i < BH_ * D_)      out[OUT_NORM_OFF + i] = past_norm[i];
}

__global__ void k_newnorm(float* __restrict__ out) {
    int bh = blockIdx.y, chunk = blockIdx.x;
    int d = threadIdx.x;
    const float* kp = g_k + ((size_t)bh * N_ + chunk * 128) * D_ + d;
    float s = 0.f;
    #pragma unroll 4
    for (int nn = 0; nn < 128; nn++) s += kp[(size_t)nn << 7];
    atomicAdd(&out[OUT_NORM_OFF + (bh << 7) + d], s);
}

__global__ void k_newkv(float* __restrict__ out) {
    __shared__ float Ksh[16][132], Vsh[16][132];
    int bh = blockIdx.y;
    int n0 = blockIdx.x << 7;
    int tid = threadIdx.x, tx = tid & 15, ty = tid >> 4;
    float acc[8][8] = {};
    const float* kbase = g_k + ((size_t)bh * N_ + n0) * D_;
    const float* vbase = g_v + ((size_t)bh * N_ + n0) * D_;
    for (int nt = 0; nt < 128; nt += 16) {
        #pragma unroll
        for (int it = 0; it < 2; it++) {
            int idx = tid + it * 256;
            int nn = idx >> 5, col = (idx & 31) << 2;
            *(float4*)&Ksh[nn][col] = *(const float4*)(kbase + (size_t)(nt + nn) * D_ + col);
            *(float4*)&Vsh[nn][col] = *(const float4*)(vbase + (size_t)(nt + nn) * D_ + col);
        }
        __syncthreads();
        #pragma unroll
        for (int nn = 0; nn < 16; nn++) {
            float a[8], b[8];
            *(float4*)(a)     = *(const float4*)&Ksh[nn][ty * 8];
            *(float4*)(a + 4) = *(const float4*)&Ksh[nn][ty * 8 + 4];
            *(float4*)(b)     = *(const float4*)&Vsh[nn][tx * 8];
            *(float4*)(b + 4) = *(const float4*)&Vsh[nn][tx * 8 + 4];
            #pragma unroll
            for (int i = 0; i < 8; i++)
                #pragma unroll
                for (int jj = 0; jj < 8; jj++)
                    acc[i][jj] = fmaf(a[i], b[jj], acc[i][jj]);
        }
        __syncthreads();
    }
    float* okv = out + OUT_KV_OFF + ((size_t)bh << 14);
    #pragma unroll
    for (int i = 0; i < 8; i++)
        #pragma unroll
        for (int jj = 0; jj < 8; jj++)
            atomicAdd(&okv[(ty * 8 + i) * 128 + tx * 8 + jj], acc[i][jj]);
}

// ---------------- 7) output GEMM (tf32 mma): d_out = g_mix @ w_out ----------------
__global__ void k_out_mma(const float* __restrict__ W, float* __restrict__ out) {
    __shared__ uint32_t As[128][40];
    __shared__ uint32_t Bs[32][136];
    int n0 = blockIdx.x * 128, m0 = blockIdx.y * 128;
    int tid = threadIdx.x, lane = tid & 31, wid = tid >> 5;
    int wm = (wid >> 2) * 64, wn = (wid & 3) * 32;
    int g = lane >> 2, t = lane & 3;
    float acc[4][4][4] = {};
    for (int k0 = 0; k0 < 1024; k0 += 32) {
        #pragma unroll
        for (int it = 0; it < 4; it++) {
            int idx = tid + it * 256;
            int am = idx >> 3, ak = (idx & 7) << 2;
            float4 a4 = *(const float4*)(g_mix + (size_t)(m0 + am) * 1024 + k0 + ak);
            uint4 au; au.x = f2t(a4.x); au.y = f2t(a4.y); au.z = f2t(a4.z); au.w = f2t(a4.w);
            *(uint4*)&As[am][ak] = au;
            int bk = idx >> 5, bn = (idx & 31) << 2;
            float4 b4 = *(const float4*)(W + (size_t)(k0 + bk) * 1024 + n0 + bn);
            uint4 bu; bu.x = f2t(b4.x); bu.y = f2t(b4.y); bu.z = f2t(b4.z); bu.w = f2t(b4.w);
            *(uint4*)&Bs[bk][bn] = bu;
        }
        __syncthreads();
        #pragma unroll
        for (int ks = 0; ks < 4; ks++) {
            int kc = ks * 8;
            uint32_t bf0[4], bf1[4];
            #pragma unroll
            for (int nt = 0; nt < 4; nt++) {
                bf0[nt] = Bs[kc + t][wn + nt * 8 + g];
                bf1[nt] = Bs[kc + t + 4][wn + nt * 8 + g];
            }
            #pragma unroll
            for (int mt = 0; mt < 4; mt++) {
                int mr = wm + mt * 16 + g;
                uint32_t a0 = As[mr][kc + t];
                uint32_t a1 = As[mr + 8][kc + t];
                uint32_t a2 = As[mr][kc + t + 4];
                uint32_t a3 = As[mr + 8][kc + t + 4];
                #pragma unroll
                for (int nt = 0; nt < 4; nt++)
                    mma8(acc[mt][nt], a0, a1, a2, a3, bf0[nt], bf1[nt]);
            }
        }
        __syncthreads();
    }
    #pragma unroll
    for (int mt = 0; mt < 4; mt++) {
        int mA = m0 + wm + mt * 16 + g;
        #pragma unroll
        for (int nt = 0; nt < 4; nt++) {
            int c = n0 + wn + nt * 8 + t * 2;
            *(float2*)&out[(size_t)mA * 1024 + c] =
                make_float2(acc[mt][nt][0], acc[mt][nt][1]);
            *(float2*)&out[(size_t)(mA + 8) * 1024 + c] =
                make_float2(acc[mt][nt][2], acc[mt][nt][3]);
        }
    }
}

// ---------------- launch ----------------
extern "C" void kernel_launch(void* const* d_in, const int* in_sizes, int n_in,
                              void* d_out, int out_size) {
    const float* x         = (const float*)d_in[0];
    const float* gamma     = (const float*)d_in[1];
    const float* w_qkv     = (const float*)d_in[2];
    const float* w_out     = (const float*)d_in[3];
    const float* gates     = (const float*)d_in[4];
    const float* past_kv   = (const float*)d_in[5];
    const float* past_norm = (const float*)d_in[6];
    float* out = (float*)d_out;

    cudaFuncSetAttribute(k_flash_mma, cudaFuncAttributeMaxDynamicSharedMemorySize, FL2_SMEM);

    k_norm<<<BN_, 256>>>(x, gamma);
    dim3 gq(24, 32);
    k_qkv_mma<<<gq, 256>>>(w_qkv);
    k_rope_table<<<(N_ * 64) / 256, 256>>>();
    k_rope_apply<<<(BH_ * N_ * 64) / 256, 256>>>();
    dim3 gf(16, 16);
    k_flash_mma<<<gf, 256, FL2_SMEM>>>();
    k_mix<<<BH_ * N_, 128>>>(past_kv, past_norm, gates);
    k_delta<<<BH_ * N_, 128>>>(past_kv, past_norm);
    k_init_out<<<1024, 256>>>(past_kv, past_norm, out);
    dim3 gn(16, 16);
    k_newnorm<<<gn, 128>>>(out);
    k_newkv<<<gn, 256>>>(out);
    dim3 go(8, 32);
    k_out_mma<<<go, 256>>>(w_out, out);
}